// round 7
// baseline (speedup 1.0000x reference)
#include <cuda_runtime.h>

// QAttentionLayer: out[..., i] = cumprod_{j<=i}( cos(x_j) * cos(w_j) )
// x: [16384, 256, 10] fp32. Rows of 10 floats; lcm(10,4)=20 -> 5-lane groups,
// each lane owns ONE contiguous float4 (perfect coalescing), cross-lane prefix
// product via 2 SHFL.IDX.
// Persistent CTAs + software-pipelined double buffer: while tile j is
// computed/stored, tile j+stride's 4 front-batched LDG.128 are in flight.
// Inner scan body identical to the proven R6 kernel.

#define NQ  10
#define ILP 4
#define GPI (6 * ILP)   // groups per warp-iteration = 24

__global__ __launch_bounds__(128)
void qattn_main(const float4* __restrict__ x4,
                float4* __restrict__ o4,
                const float* __restrict__ w,
                int n_groups, int total_iters, int warp_stride)
{
    int tid  = blockIdx.x * blockDim.x + threadIdx.x;
    int warp = tid >> 5;
    int lane = tid & 31;
    int gw   = lane / 5;          // group slot within warp tile: 0..6 (6 => idle)
    int k    = lane - gw * 5;     // float4 slot within group: 0..4
    int base = lane - k;
    bool lane_ok = (gw < 6);

    // Weight cosines for positions p = 4k..4k+3 (q = p mod 10), computed once.
    float cw0, cw1, cw2, cw3;
    {
        int p = 4 * k;
        int q0 = (p     < NQ) ? p     : p - NQ;
        int q1 = (p + 1 < NQ) ? p + 1 : p + 1 - NQ;
        int q2 = (p + 2 < NQ) ? p + 2 : p + 2 - NQ;
        int q3 = (p + 3 < NQ) ? p + 3 : p + 3 - NQ;
        cw0 = __cosf(__ldg(&w[q0]));
        cw1 = __cosf(__ldg(&w[q1]));
        cw2 = __cosf(__ldg(&w[q2]));
        cw3 = __cosf(__ldg(&w[q3]));
    }

    bool r2 = (k == 2);                          // in-thread row boundary lane
    int srcA = base + ((k >= 3) ? 2 : 0);
    int srcB = base + ((k == 4) ? 3 : 1);

    const float4 zero = make_float4(0.f, 0.f, 0.f, 0.f);

    // ---- tile load: 4 front-batched predicated LDG.128 ----
    auto load_tile = [&](int j, float4* a) {
        int g0 = j * GPI + gw;
        int b4 = g0 * 5 + k;
#pragma unroll
        for (int it = 0; it < ILP; it++) {
            bool act = lane_ok && (g0 + it * 6 < n_groups);
            a[it] = act ? __ldcs(&x4[b4 + it * 30]) : zero;
        }
    };

    // ---- tile compute + store (identical scan to R6) ----
    auto proc_tile = [&](int j, float4* a) {
        int g0 = j * GPI + gw;
        int b4 = g0 * 5 + k;
#pragma unroll
        for (int it = 0; it < ILP; it++) {
            float c0 = __cosf(a[it].x) * cw0;
            float c1 = __cosf(a[it].y) * cw1;
            float c2 = __cosf(a[it].z) * cw2;
            float c3 = __cosf(a[it].w) * cw3;

            // Local segmented inclusive scan (reset at p=10 -> k==2, j==2)
            float lp0 = c0;
            float lp1 = lp0 * c1;
            float lp2 = r2 ? c2 : lp1 * c2;
            float lp3 = lp2 * c3;

            // Cross-lane exclusive prefix (2 IDX shuffles)
            float sA = __shfl_sync(0xffffffffu, lp3, srcA);
            float sB = __shfl_sync(0xffffffffu, lp3, srcB);
            float pre = (k == 0) ? 1.0f
                      : (k == 1 || k == 3) ? sA
                      : sA * sB;
            float pre_hi = r2 ? 1.0f : pre;

            float4 r;
            r.x = lp0 * pre;
            r.y = lp1 * pre;
            r.z = lp2 * pre_hi;
            r.w = lp3 * pre_hi;

            bool act = lane_ok && (g0 + it * 6 < n_groups);
            if (act) __stcs(&o4[b4 + it * 30], r);
        }
    };

    // ---- persistent ping-pong pipeline over warp-iterations ----
    float4 A[ILP], B[ILP];
    int j = warp;
    if (j >= total_iters) return;
    load_tile(j, A);

    for (;;) {
        int jn = j + warp_stride;
        if (jn < total_iters) load_tile(jn, B);   // overlap with proc(A)
        proc_tile(j, A);
        j = jn;
        if (j >= total_iters) break;

        jn = j + warp_stride;
        if (jn < total_iters) load_tile(jn, A);   // overlap with proc(B)
        proc_tile(j, B);
        j = jn;
        if (j >= total_iters) break;
    }
}

extern "C" void kernel_launch(void* const* d_in, const int* in_sizes, int n_in,
                              void* d_out, int out_size)
{
    const float* x = (const float*)d_in[0];   // [16384*256*10] fp32
    const float* w = (const float*)d_in[1];   // [10] fp32
    float* out = (float*)d_out;

    long long total = (long long)in_sizes[0];     // 41,943,040 floats
    int n_groups    = (int)(total / 20);          // 2,097,152 groups of 20 floats
    int total_iters = (n_groups + GPI - 1) / GPI; // 87,382 warp-iterations

    int block = 128;
    int grid  = 148 * 8;                          // persistent: 1184 CTAs
    int warp_stride = grid * (block / 32);        // 4736 warps

    qattn_main<<<grid, block>>>(reinterpret_cast<const float4*>(x),
                                reinterpret_cast<float4*>(out),
                                w, n_groups, total_iters, warp_stride);
}

// round 8
// speedup vs baseline: 1.1084x; 1.1084x over previous
#include <cuda_runtime.h>

// QAttentionLayer: out[..., i] = cumprod_{j<=i}( cos(x_j) * cos(w_j) )
// x: [16384, 256, 10] fp32. Rows of 10 floats; lcm(10,4)=20 -> 5-lane groups,
// each lane owns ONE contiguous float4 (perfect coalescing), cross-lane prefix
// product via 2 SHFL.IDX. ILP=8: 8 front-batched LDG.128 per thread (MLP_p1=8).
// Single uniform predicated path (R5/R7 showed any control-flow or pipeline
// restructuring regresses). launch_bounds(256,5) caps regs at 51 -> 5 CTAs/SM.

#define NQ  10
#define ILP 8

__global__ __launch_bounds__(256, 5)
void qattn_main(const float4* __restrict__ x4,
                float4* __restrict__ o4,
                const float* __restrict__ w,
                int n_groups)
{
    int tid  = blockIdx.x * blockDim.x + threadIdx.x;
    int warp = tid >> 5;
    int lane = tid & 31;
    int gw   = lane / 5;          // group slot within warp tile: 0..6 (6 => idle)
    int k    = lane - gw * 5;     // float4 slot within group: 0..4
    int base = lane - k;          // first lane of this 5-lane group
    bool lane_ok = (gw < 6);

    // Weight cosines for positions p = 4k..4k+3 (q = p mod 10), computed once.
    float cw0, cw1, cw2, cw3;
    {
        int p = 4 * k;
        int q0 = (p     < NQ) ? p     : p - NQ;
        int q1 = (p + 1 < NQ) ? p + 1 : p + 1 - NQ;
        int q2 = (p + 2 < NQ) ? p + 2 : p + 2 - NQ;
        int q3 = (p + 3 < NQ) ? p + 3 : p + 3 - NQ;
        cw0 = __cosf(__ldg(&w[q0]));
        cw1 = __cosf(__ldg(&w[q1]));
        cw2 = __cosf(__ldg(&w[q2]));
        cw3 = __cosf(__ldg(&w[q3]));
    }

    bool r2 = (k == 2);                          // in-thread row boundary lane
    int srcA = base + ((k >= 3) ? 2 : 0);
    int srcB = base + ((k == 4) ? 3 : 1);

    int g0    = warp * (6 * ILP) + gw;           // first group of this lane
    int base4 = g0 * 5 + k;                      // its float4 index

    float4 a[ILP];
    // Front-batch ALL loads: MLP = ILP. Predicated, single path.
#pragma unroll
    for (int it = 0; it < ILP; it++) {
        bool act = lane_ok && (g0 + it * 6 < n_groups);
        a[it] = act ? __ldcs(&x4[base4 + it * 30])
                    : make_float4(0.f, 0.f, 0.f, 0.f);
    }

#pragma unroll
    for (int it = 0; it < ILP; it++) {
        float c0 = __cosf(a[it].x) * cw0;
        float c1 = __cosf(a[it].y) * cw1;
        float c2 = __cosf(a[it].z) * cw2;
        float c3 = __cosf(a[it].w) * cw3;

        // Local segmented inclusive scan (reset at p=10 -> k==2, j==2)
        float lp0 = c0;
        float lp1 = lp0 * c1;
        float lp2 = r2 ? c2 : lp1 * c2;
        float lp3 = lp2 * c3;

        // Cross-lane exclusive prefix (2 IDX shuffles)
        float sA = __shfl_sync(0xffffffffu, lp3, srcA);
        float sB = __shfl_sync(0xffffffffu, lp3, srcB);
        float pre = (k == 0) ? 1.0f
                  : (k == 1 || k == 3) ? sA
                  : sA * sB;
        float pre_hi = r2 ? 1.0f : pre;

        float4 r;
        r.x = lp0 * pre;
        r.y = lp1 * pre;
        r.z = lp2 * pre_hi;
        r.w = lp3 * pre_hi;

        bool act = lane_ok && (g0 + it * 6 < n_groups);
        if (act) __stcs(&o4[base4 + it * 30], r);
    }
}

extern "C" void kernel_launch(void* const* d_in, const int* in_sizes, int n_in,
                              void* d_out, int out_size)
{
    const float* x = (const float*)d_in[0];   // [16384*256*10] fp32
    const float* w = (const float*)d_in[1];   // [10] fp32
    float* out = (float*)d_out;

    long long total = (long long)in_sizes[0];   // 41,943,040 floats
    int n_groups    = (int)(total / 20);        // 2,097,152 groups of 20 floats
    long long warps = ((long long)n_groups + 6 * ILP - 1) / (6 * ILP);
    long long threads = warps * 32;
    int block = 256;
    long long grid = (threads + block - 1) / block;

    qattn_main<<<(unsigned)grid, block>>>(reinterpret_cast<const float4*>(x),
                                          reinterpret_cast<float4*>(out),
                                          w, n_groups);
}